// round 16
// baseline (speedup 1.0000x reference)
#include <cuda_runtime.h>
#include <cuda_bf16.h>

// RoIAlign1D: feat [B,T,D] f32, spans [B,K,2] i32, lengths [B] i32 -> out [B,K,P,D] f32
// P = 16, D = 512 (128 float4).
//
// FINAL = R13, the measured optimum over 15 rounds (10.688us wall, 11.04us ncu):
//   - one block per (RoI, 2-sample group): grid B*K*8 = 8192, 128 threads
//   - 4 independent LDG.128 per thread (MLP_p1=4: measured best point on the
//     MLP x occupancy frontier; MLP 8 triggered cross-CTA L1tex-queue spread
//     (occ 57%), MLP 2 undershot latency hiding)
//   - default L1-cached feat loads (cross-group row reuse is real; __ldcg
//     regressed 2.1us), __stcs streaming stores (best measured store policy;
//     the 30MB/replay DRAM write stream is compulsory either way)
//   - w==0 load dedup: i1 <- i0 when the lerp weight is zero (p=0, p=15,
//     integral t*segm1) -- f1 is multiplied by zero, output bit-identical,
//     second L2 read merges away (~6% read traffic)
//   - __launch_bounds__(128,16): 30 regs, 64-warp/SM occupancy cap
// Rejected by measurement: persistent grids (x2), software pipelining,
// f32x2 packed math, v8.f32 256-bit ops, write-back stores, fused item
// pairs, int2 span load. All landed 10.98-13.0us.

#define P_SAMPLES 16
#define PG 2   // samples per block

__global__ void __launch_bounds__(128, 16) roialign1d_kernel(
    const float4* __restrict__ feat,   // [B, T, 128]
    const int*    __restrict__ spans,  // [B, K, 2]
    const int*    __restrict__ lengths,// [B]
    float4*       __restrict__ out,    // [B, K, P, 128]
    int K, int T, int D4)
{
    const int blk = blockIdx.x;                  // bk*8 + pg
    const int pg  = blk & 7;
    const int bk  = blk >> 3;                    // b*K + k
    const int b   = bk / K;
    const int tid = threadIdx.x;                 // d4 lane, 0..127

    // ---- span math, once per block (uniform) ----
    const int Lm1 = __ldg(&lengths[b]) - 1;
    int a0 = __ldg(&spans[bk * 2 + 0]);
    int a1 = __ldg(&spans[bk * 2 + 1]);
    a0 = min(max(a0, 0), Lm1);
    a1 = min(max(a1, 0), Lm1);
    const int s     = min(a0, a1);
    const int segm1 = max(a0, a1) - s;           // seglen - 1
    const float segf = (float)segm1;

    const int fbase = (b * T + s) * D4 + tid;
    const int obase = (bk * P_SAMPLES + pg * PG) * D4 + tid;

    float4 f0[PG], f1[PG];
    float  w[PG];
    #pragma unroll
    for (int u = 0; u < PG; u++) {
        const int pp = pg * PG + u;
        const float t   = (float)pp / (float)(P_SAMPLES - 1);
        const float idx = t * segf;
        int i0 = (int)floorf(idx);
        i0 = min(i0, segm1);
        int i1 = min(i0 + 1, segm1);
        w[u] = idx - (float)i0;
        if (w[u] == 0.0f) i1 = i0;               // f1 unused when w==0: dedupe load
        f0[u] = feat[fbase + i0 * D4];
        f1[u] = feat[fbase + i1 * D4];
    }
    #pragma unroll
    for (int u = 0; u < PG; u++) {
        float4 r;
        r.x = fmaf(w[u], f1[u].x - f0[u].x, f0[u].x);
        r.y = fmaf(w[u], f1[u].y - f0[u].y, f0[u].y);
        r.z = fmaf(w[u], f1[u].z - f0[u].z, f0[u].z);
        r.w = fmaf(w[u], f1[u].w - f0[u].w, f0[u].w);
        __stcs(&out[obase + u * D4], r);         // streaming store (best measured)
    }
}

extern "C" void kernel_launch(void* const* d_in, const int* in_sizes, int n_in,
                              void* d_out, int out_size)
{
    const float* feat    = (const float*)d_in[0];
    const int*   spans   = (const int*)d_in[1];
    const int*   lengths = (const int*)d_in[2];
    float*       out     = (float*)d_out;

    const int B  = in_sizes[2];                      // 16
    const int K  = in_sizes[1] / (2 * B);            // 64
    const int TD = in_sizes[0] / B;                  // T*D
    const int D  = out_size / (B * K * P_SAMPLES);   // 512
    const int T  = TD / D;                           // 4096
    const int D4 = D / 4;                            // 128

    const int nblocks = B * K * (P_SAMPLES / PG);    // 8192
    roialign1d_kernel<<<nblocks, D4>>>(
        (const float4*)feat, spans, lengths, (float4*)out, K, T, D4);
}